// round 4
// baseline (speedup 1.0000x reference)
#include <cuda_runtime.h>
#include <cstdint>

#define N_NODES 100000
#define N_EDGES 1600000
#define F_IN    100
#define F_H     32

// ---------------- scratch (static device globals; no runtime allocs) ---------
__device__ float g_deg [N_NODES];
__device__ float g_dinv[N_NODES];
__device__ __align__(16) float g_hs [(size_t)N_NODES * F_H];  // h * dinv[src]
__device__ __align__(16) float g_agg[(size_t)N_NODES * F_H];  // aggregated
__device__ int   g_is32;                                      // 1 if edge_index is int32

// Edge index accessor: works for int32 or int64 storage.
__device__ __forceinline__ int edge_at(const void* ei, size_t i, int is32) {
    if (is32) return ((const int*)ei)[i];
    return (int)((const long long*)ei)[i];
}

// ---------------- K0: dtype detection (single block, deterministic) ----------
__global__ void k_detect(const void* ei, int n_total, int n_nodes) {
    __shared__ int bad;
    if (threadIdx.x == 0) bad = 0;
    __syncthreads();
    int n_check = n_total < 2048 ? n_total : 2048;
    for (int i = threadIdx.x; i < n_check; i += blockDim.x) {
        long long v = ((const long long*)ei)[i];
        if (v < 0 || v >= (long long)n_nodes) atomicOr(&bad, 1);
    }
    __syncthreads();
    if (threadIdx.x == 0) g_is32 = bad;   // int64-read garbage => data is int32
}

// ---------------- K1: deg init (self loop contributes 1) ---------------------
__global__ void k_init_deg(int n) {
    int i = blockIdx.x * blockDim.x + threadIdx.x;
    if (i < n) g_deg[i] = 1.0f;
}

// ---------------- K2: degree accumulation over edges -------------------------
__global__ void k_degree(const void* __restrict__ edge_index, int n_edges) {
    int e = blockIdx.x * blockDim.x + threadIdx.x;
    if (e < n_edges) {
        int is32 = g_is32;
        int dst = edge_at(edge_index, (size_t)n_edges + e, is32);
        atomicAdd(&g_deg[dst], 1.0f);
    }
}

// ---------------- K3: h = x @ W (no bias), hs = h*dinv, agg = hs*dinv --------
// block: 32 cols x 8 rows = 256 threads. W (100x32) cached in smem.
__global__ void k_gemm(const float* __restrict__ x,
                       const float* __restrict__ W,
                       int n_nodes) {
    __shared__ float Ws[F_IN * F_H];
    int tid = threadIdx.y * 32 + threadIdx.x;
    for (int i = tid; i < F_IN * F_H; i += 256) Ws[i] = W[i];
    __syncthreads();

    int row = blockIdx.x * 8 + threadIdx.y;
    if (row >= n_nodes) return;
    int col = threadIdx.x;

    const float* xr = x + (size_t)row * F_IN;
    float acc = 0.0f;
#pragma unroll 4
    for (int k = 0; k < F_IN; k++) {
        acc = fmaf(__ldg(&xr[k]), Ws[k * F_H + col], acc);
    }
    float dinv = rsqrtf(g_deg[row]);
    if (col == 0) g_dinv[row] = dinv;
    float hsv = acc * dinv;
    size_t o = (size_t)row * F_H + col;
    g_hs[o]  = hsv;
    g_agg[o] = hsv * dinv;   // self-loop term: h*dinv*dinv
}

// ---------------- K4: edge scatter, scalar atomicAdd (RED.E.ADD.F32) ---------
// 8 lanes per edge; each lane handles 4 consecutive features.
__global__ void k_scatter(const void* __restrict__ edge_index, int n_edges) {
    int t = blockIdx.x * blockDim.x + threadIdx.x;
    int e = t >> 3;
    int g = t & 7;
    if (e >= n_edges) return;
    int is32 = g_is32;
    int src = edge_at(edge_index, e, is32);
    int dst = edge_at(edge_index, (size_t)n_edges + e, is32);

    const float4* hsv4 = (const float4*)g_hs;
    float4 v = __ldg(&hsv4[(size_t)src * 8 + g]);
    float s = __ldg(&g_dinv[dst]);

    float* p = &g_agg[(size_t)dst * F_H + g * 4];
    atomicAdd(p + 0, v.x * s);
    atomicAdd(p + 1, v.y * s);
    atomicAdd(p + 2, v.z * s);
    atomicAdd(p + 3, v.w * s);
}

// ---------------- K5: bias + relu + MLP + log_softmax ------------------------
__global__ void k_mlp(const float* __restrict__ b_conv,
                      const float* __restrict__ W1, const float* __restrict__ b1,
                      const float* __restrict__ W2, const float* __restrict__ b2,
                      const float* __restrict__ W3, const float* __restrict__ b3,
                      float* __restrict__ out, int n_nodes) {
    __shared__ float sW1[32 * 16], sb1[16];
    __shared__ float sW2[16 * 8],  sb2[8];
    __shared__ float sW3[8 * 10],  sb3[10];
    __shared__ float sbc[32];
    int tid = threadIdx.x;
    for (int i = tid; i < 32 * 16; i += blockDim.x) sW1[i] = W1[i];
    for (int i = tid; i < 16 * 8;  i += blockDim.x) sW2[i] = W2[i];
    for (int i = tid; i < 8 * 10;  i += blockDim.x) sW3[i] = W3[i];
    if (tid < 16) sb1[tid] = b1[tid];
    if (tid < 8)  sb2[tid] = b2[tid];
    if (tid < 10) sb3[tid] = b3[tid];
    if (tid < 32) sbc[tid] = b_conv[tid];
    __syncthreads();

    int node = blockIdx.x * blockDim.x + tid;
    if (node >= n_nodes) return;

    // load agg row, add conv bias, relu
    float a[32];
    const float4* ag4 = (const float4*)(&g_agg[(size_t)node * F_H]);
#pragma unroll
    for (int q = 0; q < 8; q++) {
        float4 v = ag4[q];
        a[q * 4 + 0] = fmaxf(v.x + sbc[q * 4 + 0], 0.0f);
        a[q * 4 + 1] = fmaxf(v.y + sbc[q * 4 + 1], 0.0f);
        a[q * 4 + 2] = fmaxf(v.z + sbc[q * 4 + 2], 0.0f);
        a[q * 4 + 3] = fmaxf(v.w + sbc[q * 4 + 3], 0.0f);
    }

    // 32 -> 16 relu
    float h1[16];
#pragma unroll
    for (int j = 0; j < 16; j++) {
        float s = sb1[j];
#pragma unroll
        for (int k = 0; k < 32; k++) s = fmaf(a[k], sW1[k * 16 + j], s);
        h1[j] = fmaxf(s, 0.0f);
    }
    // 16 -> 8 relu
    float h2[8];
#pragma unroll
    for (int j = 0; j < 8; j++) {
        float s = sb2[j];
#pragma unroll
        for (int k = 0; k < 16; k++) s = fmaf(h1[k], sW2[k * 8 + j], s);
        h2[j] = fmaxf(s, 0.0f);
    }
    // 8 -> 10
    float z[10];
#pragma unroll
    for (int j = 0; j < 10; j++) {
        float s = sb3[j];
#pragma unroll
        for (int k = 0; k < 8; k++) s = fmaf(h2[k], sW3[k * 10 + j], s);
        z[j] = s;
    }
    // log_softmax
    float m = z[0];
#pragma unroll
    for (int j = 1; j < 10; j++) m = fmaxf(m, z[j]);
    float sum = 0.0f;
#pragma unroll
    for (int j = 0; j < 10; j++) sum += expf(z[j] - m);
    float lse = logf(sum) + m;
    float* op = out + (size_t)node * 10;
#pragma unroll
    for (int j = 0; j < 10; j++) op[j] = z[j] - lse;
}

// ---------------- launch -----------------------------------------------------
extern "C" void kernel_launch(void* const* d_in, const int* in_sizes, int n_in,
                              void* d_out, int out_size) {
    const float* x          = (const float*)d_in[0];
    const void*  edge_index = (const void*)d_in[1];
    // d_in[2] = edge_weight (unused by reference)
    const float* W_conv = (const float*)d_in[3];
    const float* b_conv = (const float*)d_in[4];
    const float* W1 = (const float*)d_in[5];
    const float* b1 = (const float*)d_in[6];
    const float* W2 = (const float*)d_in[7];
    const float* b2 = (const float*)d_in[8];
    const float* W3 = (const float*)d_in[9];
    const float* b3 = (const float*)d_in[10];
    float* out = (float*)d_out;

    int n_nodes = in_sizes[0] / F_IN;     // 100000
    int n_edges = in_sizes[1] / 2;        // 1600000 (element count / 2, dtype-agnostic)

    k_detect<<<1, 256>>>(edge_index, in_sizes[1], n_nodes);
    k_init_deg<<<(n_nodes + 255) / 256, 256>>>(n_nodes);
    k_degree<<<(n_edges + 255) / 256, 256>>>(edge_index, n_edges);

    dim3 gblk(32, 8);
    k_gemm<<<(n_nodes + 7) / 8, gblk>>>(x, W_conv, n_nodes);

    long long scatter_threads = (long long)n_edges * 8;
    k_scatter<<<(int)((scatter_threads + 255) / 256), 256>>>(edge_index, n_edges);

    k_mlp<<<(n_nodes + 127) / 128, 128>>>(b_conv, W1, b1, W2, b2, W3, b3,
                                          out, n_nodes);
}

// round 5
// speedup vs baseline: 1.8324x; 1.8324x over previous
#include <cuda_runtime.h>
#include <cstdint>

#define N_NODES 100000
#define N_EDGES 1600000
#define F_IN    100
#define F_H     32
#define GR      64   // rows per gemm block

// ---------------- scratch (static device globals; no runtime allocs) ---------
__device__ float g_deg [N_NODES];
__device__ float g_dinv[N_NODES];
__device__ __align__(16) float g_hs [(size_t)N_NODES * F_H];  // h * dinv[src]
__device__ __align__(16) float g_agg[(size_t)N_NODES * F_H];  // aggregated
__device__ int   g_is32;                                      // 1 if edge_index is int32

// Edge index accessor: works for int32 or int64 storage.
__device__ __forceinline__ int edge_at(const void* ei, size_t i, int is32) {
    if (is32) return ((const int*)ei)[i];
    return (int)((const long long*)ei)[i];
}

// ---------------- K0: dtype detection (single block, deterministic) ----------
__global__ void k_detect(const void* ei, int n_total, int n_nodes) {
    __shared__ int bad;
    if (threadIdx.x == 0) bad = 0;
    __syncthreads();
    int n_check = n_total < 2048 ? n_total : 2048;
    for (int i = threadIdx.x; i < n_check; i += blockDim.x) {
        long long v = ((const long long*)ei)[i];
        if (v < 0 || v >= (long long)n_nodes) atomicOr(&bad, 1);
    }
    __syncthreads();
    if (threadIdx.x == 0) g_is32 = bad;   // int64-read garbage => data is int32
}

// ---------------- K1: deg init (self loop contributes 1) ---------------------
__global__ void k_init_deg(int n) {
    int i = blockIdx.x * blockDim.x + threadIdx.x;
    if (i < n) g_deg[i] = 1.0f;
}

// ---------------- K2: degree accumulation over edges -------------------------
__global__ void k_degree(const void* __restrict__ edge_index, int n_edges) {
    int e = blockIdx.x * blockDim.x + threadIdx.x;
    if (e < n_edges) {
        int is32 = g_is32;
        int dst = edge_at(edge_index, (size_t)n_edges + e, is32);
        atomicAdd(&g_deg[dst], 1.0f);
    }
}

// ---------------- K3: tiled GEMM: h = x@W, hs = h*dinv, agg = hs*dinv --------
// 256 threads, 64 rows/block, 8 cols/thread. x tile + W staged in smem.
__global__ void __launch_bounds__(256) k_gemm(const float* __restrict__ x,
                                              const float* __restrict__ W,
                                              int n_nodes) {
    __shared__ float xs[GR * F_IN];       // 25.6 KB
    __shared__ float Ws[F_IN * F_H];      // 12.8 KB
    int tid = threadIdx.x;
    int row0 = blockIdx.x * GR;

    // stage W (800 float4)
    const float4* W4 = (const float4*)W;
    for (int i = tid; i < (F_IN * F_H) / 4; i += 256)
        ((float4*)Ws)[i] = W4[i];
    // stage x tile: rows are 400B (16B-aligned) -> float4 loads
    const float4* x4 = (const float4*)x;
    int nrow = n_nodes - row0; if (nrow > GR) nrow = GR;
    for (int i = tid; i < nrow * (F_IN / 4); i += 256) {
        int r = i / (F_IN / 4), c = i % (F_IN / 4);
        ((float4*)xs)[r * (F_IN / 4) + c] = x4[(size_t)(row0 + r) * (F_IN / 4) + c];
    }
    __syncthreads();

    int r  = tid >> 2;             // 0..63
    int cg = (tid & 3) * 8;        // col base: 0,8,16,24
    int row = row0 + r;
    if (row >= n_nodes) return;

    float acc[8];
#pragma unroll
    for (int j = 0; j < 8; j++) acc[j] = 0.0f;

    const float* xr = xs + r * F_IN;
#pragma unroll 10
    for (int k = 0; k < F_IN; k++) {
        float xv = xr[k];
        float4 w0 = *(const float4*)&Ws[k * F_H + cg];
        float4 w1 = *(const float4*)&Ws[k * F_H + cg + 4];
        acc[0] = fmaf(xv, w0.x, acc[0]);
        acc[1] = fmaf(xv, w0.y, acc[1]);
        acc[2] = fmaf(xv, w0.z, acc[2]);
        acc[3] = fmaf(xv, w0.w, acc[3]);
        acc[4] = fmaf(xv, w1.x, acc[4]);
        acc[5] = fmaf(xv, w1.y, acc[5]);
        acc[6] = fmaf(xv, w1.z, acc[6]);
        acc[7] = fmaf(xv, w1.w, acc[7]);
    }

    float dinv = rsqrtf(g_deg[row]);
    if ((tid & 3) == 0) g_dinv[row] = dinv;

    size_t o = (size_t)row * F_H + cg;
    float4 h0, h1, a0, a1;
    h0.x = acc[0]*dinv; h0.y = acc[1]*dinv; h0.z = acc[2]*dinv; h0.w = acc[3]*dinv;
    h1.x = acc[4]*dinv; h1.y = acc[5]*dinv; h1.z = acc[6]*dinv; h1.w = acc[7]*dinv;
    a0.x = h0.x*dinv; a0.y = h0.y*dinv; a0.z = h0.z*dinv; a0.w = h0.w*dinv;
    a1.x = h1.x*dinv; a1.y = h1.y*dinv; a1.z = h1.z*dinv; a1.w = h1.w*dinv;
    *(float4*)&g_hs[o]      = h0;
    *(float4*)&g_hs[o + 4]  = h1;
    *(float4*)&g_agg[o]     = a0;   // self-loop term: h*dinv*dinv
    *(float4*)&g_agg[o + 4] = a1;
}

// ---------------- K4: edge scatter, vector red.global.add.v4.f32 -------------
// 8 lanes per edge; each lane handles 4 consecutive features, 1 RED op.
__global__ void k_scatter(const void* __restrict__ edge_index, int n_edges) {
    int t = blockIdx.x * blockDim.x + threadIdx.x;
    int e = t >> 3;
    int g = t & 7;
    if (e >= n_edges) return;
    int is32 = g_is32;
    int src = edge_at(edge_index, e, is32);
    int dst = edge_at(edge_index, (size_t)n_edges + e, is32);

    const float4* hsv4 = (const float4*)g_hs;
    float4 v = __ldg(&hsv4[(size_t)src * 8 + g]);
    float s = __ldg(&g_dinv[dst]);

    float* p = &g_agg[(size_t)dst * F_H + g * 4];
    asm volatile("red.global.add.v4.f32 [%0], {%1, %2, %3, %4};"
                 :: "l"(p), "f"(v.x * s), "f"(v.y * s), "f"(v.z * s), "f"(v.w * s)
                 : "memory");
}

// ---------------- K5: bias + relu + MLP + log_softmax ------------------------
__global__ void k_mlp(const float* __restrict__ b_conv,
                      const float* __restrict__ W1, const float* __restrict__ b1,
                      const float* __restrict__ W2, const float* __restrict__ b2,
                      const float* __restrict__ W3, const float* __restrict__ b3,
                      float* __restrict__ out, int n_nodes) {
    __shared__ float sW1[32 * 16], sb1[16];
    __shared__ float sW2[16 * 8],  sb2[8];
    __shared__ float sW3[8 * 10],  sb3[10];
    __shared__ float sbc[32];
    int tid = threadIdx.x;
    for (int i = tid; i < 32 * 16; i += blockDim.x) sW1[i] = W1[i];
    for (int i = tid; i < 16 * 8;  i += blockDim.x) sW2[i] = W2[i];
    for (int i = tid; i < 8 * 10;  i += blockDim.x) sW3[i] = W3[i];
    if (tid < 16) sb1[tid] = b1[tid];
    if (tid < 8)  sb2[tid] = b2[tid];
    if (tid < 10) sb3[tid] = b3[tid];
    if (tid < 32) sbc[tid] = b_conv[tid];
    __syncthreads();

    int node = blockIdx.x * blockDim.x + tid;
    if (node >= n_nodes) return;

    float a[32];
    const float4* ag4 = (const float4*)(&g_agg[(size_t)node * F_H]);
#pragma unroll
    for (int q = 0; q < 8; q++) {
        float4 v = ag4[q];
        a[q * 4 + 0] = fmaxf(v.x + sbc[q * 4 + 0], 0.0f);
        a[q * 4 + 1] = fmaxf(v.y + sbc[q * 4 + 1], 0.0f);
        a[q * 4 + 2] = fmaxf(v.z + sbc[q * 4 + 2], 0.0f);
        a[q * 4 + 3] = fmaxf(v.w + sbc[q * 4 + 3], 0.0f);
    }

    float h1[16];
#pragma unroll
    for (int j = 0; j < 16; j++) {
        float s = sb1[j];
#pragma unroll
        for (int k = 0; k < 32; k++) s = fmaf(a[k], sW1[k * 16 + j], s);
        h1[j] = fmaxf(s, 0.0f);
    }
    float h2[8];
#pragma unroll
    for (int j = 0; j < 8; j++) {
        float s = sb2[j];
#pragma unroll
        for (int k = 0; k < 16; k++) s = fmaf(h1[k], sW2[k * 8 + j], s);
        h2[j] = fmaxf(s, 0.0f);
    }
    float z[10];
#pragma unroll
    for (int j = 0; j < 10; j++) {
        float s = sb3[j];
#pragma unroll
        for (int k = 0; k < 8; k++) s = fmaf(h2[k], sW3[k * 10 + j], s);
        z[j] = s;
    }
    float m = z[0];
#pragma unroll
    for (int j = 1; j < 10; j++) m = fmaxf(m, z[j]);
    float sum = 0.0f;
#pragma unroll
    for (int j = 0; j < 10; j++) sum += expf(z[j] - m);
    float lse = logf(sum) + m;
    float* op = out + (size_t)node * 10;
#pragma unroll
    for (int j = 0; j < 10; j++) op[j] = z[j] - lse;
}

// ---------------- launch -----------------------------------------------------
extern "C" void kernel_launch(void* const* d_in, const int* in_sizes, int n_in,
                              void* d_out, int out_size) {
    const float* x          = (const float*)d_in[0];
    const void*  edge_index = (const void*)d_in[1];
    // d_in[2] = edge_weight (unused by reference)
    const float* W_conv = (const float*)d_in[3];
    const float* b_conv = (const float*)d_in[4];
    const float* W1 = (const float*)d_in[5];
    const float* b1 = (const float*)d_in[6];
    const float* W2 = (const float*)d_in[7];
    const float* b2 = (const float*)d_in[8];
    const float* W3 = (const float*)d_in[9];
    const float* b3 = (const float*)d_in[10];
    float* out = (float*)d_out;

    int n_nodes = in_sizes[0] / F_IN;     // 100000
    int n_edges = in_sizes[1] / 2;        // 1600000 (element count / 2)

    k_detect<<<1, 256>>>(edge_index, in_sizes[1], n_nodes);
    k_init_deg<<<(n_nodes + 255) / 256, 256>>>(n_nodes);
    k_degree<<<(n_edges + 255) / 256, 256>>>(edge_index, n_edges);

    k_gemm<<<(n_nodes + GR - 1) / GR, 256>>>(x, W_conv, n_nodes);

    long long scatter_threads = (long long)n_edges * 8;
    k_scatter<<<(int)((scatter_threads + 255) / 256), 256>>>(edge_index, n_edges);

    k_mlp<<<(n_nodes + 127) / 128, 128>>>(b_conv, W1, b1, W2, b2, W3, b3,
                                          out, n_nodes);
}

// round 8
// speedup vs baseline: 2.1562x; 1.1767x over previous
#include <cuda_runtime.h>
#include <cstdint>

#define N_NODES 100000
#define N_EDGES 1600000
#define F_IN    100
#define F_H     32
#define GROWS   128   // rows per gemm block (2 per thread, 256 threads)

typedef unsigned long long ull;

// ---------------- scratch (static device globals; no runtime allocs) ---------
__device__ float g_deg [N_NODES];
__device__ float g_dinv[N_NODES];
__device__ __align__(16) float g_hs [(size_t)N_NODES * F_H];  // h * dinv[src]
__device__ __align__(16) float g_agg[(size_t)N_NODES * F_H];  // raw aggregate
__device__ int   g_is32;                                      // 1 if edge_index is int32

__device__ __forceinline__ int edge_at(const void* ei, size_t i, int is32) {
    if (is32) return ((const int*)ei)[i];
    return (int)((const long long*)ei)[i];
}

// packed fp32x2 helpers (sm_100+)
__device__ __forceinline__ void fma2(ull& d, ull a, ull b) {
    asm("fma.rn.f32x2 %0, %1, %2, %0;" : "+l"(d) : "l"(a), "l"(b));
}
__device__ __forceinline__ ull dup2(float v) {
    ull r; asm("mov.b64 %0, {%1, %1};" : "=l"(r) : "f"(v)); return r;
}
__device__ __forceinline__ void unpk(ull v, float& lo, float& hi) {
    asm("mov.b64 {%0, %1}, %2;" : "=f"(lo), "=f"(hi) : "l"(v));
}

// ---------------- K0: dtype detection (single block, deterministic) ----------
__global__ void k_detect(const void* ei, int n_total, int n_nodes) {
    __shared__ int bad;
    if (threadIdx.x == 0) bad = 0;
    __syncthreads();
    int n_check = n_total < 2048 ? n_total : 2048;
    for (int i = threadIdx.x; i < n_check; i += blockDim.x) {
        long long v = ((const long long*)ei)[i];
        if (v < 0 || v >= (long long)n_nodes) atomicOr(&bad, 1);
    }
    __syncthreads();
    if (threadIdx.x == 0) g_is32 = bad;
}

// ---------------- K1: deg init (self loop contributes 1) ---------------------
__global__ void k_init_deg(int n) {
    int i = blockIdx.x * blockDim.x + threadIdx.x;
    if (i < n) g_deg[i] = 1.0f;
}

// ---------------- K2: degree accumulation over edges -------------------------
__global__ void k_degree(const void* __restrict__ edge_index, int n_edges) {
    int e = blockIdx.x * blockDim.x + threadIdx.x;
    if (e < n_edges) {
        int dst = edge_at(edge_index, (size_t)n_edges + e, g_is32);
        atomicAdd(&g_deg[dst], 1.0f);
    }
}

// ---------------- K3: GEMM h = x@W with f32x2 packed FMA ---------------------
// 256 threads: thread = 2 rows x 8 cols. W in smem (read as ulonglong2 = 2 col
// pairs per LDS.128, no packing movs). x read directly via LDG.128.
// W row (32 floats = 128B) = 8 ulonglong2; thread cq uses indices k*8+cq*2, +1.
__global__ void __launch_bounds__(256) k_gemm(const float* __restrict__ x,
                                              const float* __restrict__ W,
                                              int n_nodes) {
    __shared__ __align__(16) float Ws[F_IN * F_H];   // 12.8 KB
    int tid = threadIdx.x;
    const float4* W4 = (const float4*)W;
    for (int i = tid; i < (F_IN * F_H) / 4; i += 256)
        ((float4*)Ws)[i] = W4[i];
    __syncthreads();

    int rt = tid >> 2;                  // 0..63 row-pair index
    int cq = (tid & 3);                 // col quarter: cols cq*8 .. cq*8+7
    int r0 = blockIdx.x * GROWS + rt * 2;
    int r1 = r0 + 1;
    if (r0 >= n_nodes) return;
    int rd1 = r1 < n_nodes ? r1 : r0;   // clamped read row (store guarded)

    const float4* x0 = (const float4*)x + (size_t)r0  * (F_IN / 4);
    const float4* x1 = (const float4*)x + (size_t)rd1 * (F_IN / 4);
    const ulonglong2* Wp = (const ulonglong2*)Ws;

    ull acc0[4], acc1[4];
#pragma unroll
    for (int p = 0; p < 4; p++) { acc0[p] = 0ull; acc1[p] = 0ull; }

#pragma unroll 5
    for (int c = 0; c < F_IN / 4; c++) {
        float4 xa = __ldg(&x0[c]);
        float4 xb = __ldg(&x1[c]);
        float va[4] = {xa.x, xa.y, xa.z, xa.w};
        float vb[4] = {xb.x, xb.y, xb.z, xb.w};
#pragma unroll
        for (int kk = 0; kk < 4; kk++) {
            int k = c * 4 + kk;
            ulonglong2 wA = Wp[k * 8 + cq * 2];      // pairs: cols cq*8+0..3
            ulonglong2 wB = Wp[k * 8 + cq * 2 + 1];  // pairs: cols cq*8+4..7
            ull a0 = dup2(va[kk]);
            ull a1 = dup2(vb[kk]);
            fma2(acc0[0], a0, wA.x); fma2(acc0[1], a0, wA.y);
            fma2(acc0[2], a0, wB.x); fma2(acc0[3], a0, wB.y);
            fma2(acc1[0], a1, wA.x); fma2(acc1[1], a1, wA.y);
            fma2(acc1[2], a1, wB.x); fma2(acc1[3], a1, wB.y);
        }
    }

    // epilogue: hs = h * dinv[row]; write g_hs and g_agg (raw init = self-loop)
    {
        float dinv = rsqrtf(g_deg[r0]);
        if (cq == 0) g_dinv[r0] = dinv;
        float o[8];
#pragma unroll
        for (int p = 0; p < 4; p++) unpk(acc0[p], o[p * 2], o[p * 2 + 1]);
        float4 v0 = {o[0]*dinv, o[1]*dinv, o[2]*dinv, o[3]*dinv};
        float4 v1 = {o[4]*dinv, o[5]*dinv, o[6]*dinv, o[7]*dinv};
        size_t off = (size_t)r0 * F_H + cq * 8;
        *(float4*)&g_hs [off]     = v0;  *(float4*)&g_hs [off + 4] = v1;
        *(float4*)&g_agg[off]     = v0;  *(float4*)&g_agg[off + 4] = v1;
    }
    if (r1 < n_nodes) {
        float dinv = rsqrtf(g_deg[r1]);
        if (cq == 0) g_dinv[r1] = dinv;
        float o[8];
#pragma unroll
        for (int p = 0; p < 4; p++) unpk(acc1[p], o[p * 2], o[p * 2 + 1]);
        float4 v0 = {o[0]*dinv, o[1]*dinv, o[2]*dinv, o[3]*dinv};
        float4 v1 = {o[4]*dinv, o[5]*dinv, o[6]*dinv, o[7]*dinv};
        size_t off = (size_t)r1 * F_H + cq * 8;
        *(float4*)&g_hs [off]     = v0;  *(float4*)&g_hs [off + 4] = v1;
        *(float4*)&g_agg[off]     = v0;  *(float4*)&g_agg[off + 4] = v1;
    }
}

// ---------------- K4: pure gather + vector RED (dinv[dst] deferred) ----------
__global__ void k_scatter(const void* __restrict__ edge_index, int n_edges) {
    int t = blockIdx.x * blockDim.x + threadIdx.x;
    int e = t >> 3;
    int g = t & 7;
    if (e >= n_edges) return;
    int is32 = g_is32;
    int src = edge_at(edge_index, e, is32);
    int dst = edge_at(edge_index, (size_t)n_edges + e, is32);

    const float4* hsv4 = (const float4*)g_hs;
    float4 v = __ldg(&hsv4[(size_t)src * 8 + g]);

    float* p = &g_agg[(size_t)dst * F_H + g * 4];
    asm volatile("red.global.add.v4.f32 [%0], {%1, %2, %3, %4};"
                 :: "l"(p), "f"(v.x), "f"(v.y), "f"(v.z), "f"(v.w)
                 : "memory");
}

// ---------------- K5: dinv scale + bias + relu + MLP + log_softmax -----------
__global__ void k_mlp(const float* __restrict__ b_conv,
                      const float* __restrict__ W1, const float* __restrict__ b1,
                      const float* __restrict__ W2, const float* __restrict__ b2,
                      const float* __restrict__ W3, const float* __restrict__ b3,
                      float* __restrict__ out, int n_nodes) {
    __shared__ float sW1[32 * 16], sb1[16];
    __shared__ float sW2[16 * 8],  sb2[8];
    __shared__ float sW3[8 * 10],  sb3[10];
    __shared__ float sbc[32];
    int tid = threadIdx.x;
    for (int i = tid; i < 32 * 16; i += blockDim.x) sW1[i] = W1[i];
    for (int i = tid; i < 16 * 8;  i += blockDim.x) sW2[i] = W2[i];
    for (int i = tid; i < 8 * 10;  i += blockDim.x) sW3[i] = W3[i];
    if (tid < 16) sb1[tid] = b1[tid];
    if (tid < 8)  sb2[tid] = b2[tid];
    if (tid < 10) sb3[tid] = b3[tid];
    if (tid < 32) sbc[tid] = b_conv[tid];
    __syncthreads();

    int node = blockIdx.x * blockDim.x + tid;
    if (node >= n_nodes) return;

    float dinv = g_dinv[node];
    float a[32];
    const float4* ag4 = (const float4*)(&g_agg[(size_t)node * F_H]);
#pragma unroll
    for (int q = 0; q < 8; q++) {
        float4 v = ag4[q];
        a[q * 4 + 0] = fmaxf(fmaf(v.x, dinv, sbc[q * 4 + 0]), 0.0f);
        a[q * 4 + 1] = fmaxf(fmaf(v.y, dinv, sbc[q * 4 + 1]), 0.0f);
        a[q * 4 + 2] = fmaxf(fmaf(v.z, dinv, sbc[q * 4 + 2]), 0.0f);
        a[q * 4 + 3] = fmaxf(fmaf(v.w, dinv, sbc[q * 4 + 3]), 0.0f);
    }

    float h1[16];
#pragma unroll
    for (int j = 0; j < 16; j++) {
        float s = sb1[j];
#pragma unroll
        for (int k = 0; k < 32; k++) s = fmaf(a[k], sW1[k * 16 + j], s);
        h1[j] = fmaxf(s, 0.0f);
    }
    float h2[8];
#pragma unroll
    for (int j = 0; j < 8; j++) {
        float s = sb2[j];
#pragma unroll
        for (int k = 0; k < 16; k++) s = fmaf(h1[k], sW2[k * 8 + j], s);
        h2[j] = fmaxf(s, 0.0f);
    }
    float z[10];
#pragma unroll
    for (int j = 0; j < 10; j++) {
        float s = sb3[j];
#pragma unroll
        for (int k = 0; k < 8; k++) s = fmaf(h2[k], sW3[k * 10 + j], s);
        z[j] = s;
    }
    float m = z[0];
#pragma unroll
    for (int j = 1; j < 10; j++) m = fmaxf(m, z[j]);
    float sum = 0.0f;
#pragma unroll
    for (int j = 0; j < 10; j++) sum += expf(z[j] - m);
    float lse = logf(sum) + m;
    float* op = out + (size_t)node * 10;
#pragma unroll
    for (int j = 0; j < 10; j++) op[j] = z[j] - lse;
}

// ---------------- launch -----------------------------------------------------
extern "C" void kernel_launch(void* const* d_in, const int* in_sizes, int n_in,
                              void* d_out, int out_size) {
    const float* x          = (const float*)d_in[0];
    const void*  edge_index = (const void*)d_in[1];
    const float* W_conv = (const float*)d_in[3];
    const float* b_conv = (const float*)d_in[4];
    const float* W1 = (const float*)d_in[5];
    const float* b1 = (const float*)d_in[6];
    const float* W2 = (const float*)d_in[7];
    const float* b2 = (const float*)d_in[8];
    const float* W3 = (const float*)d_in[9];
    const float* b3 = (const float*)d_in[10];
    float* out = (float*)d_out;

    int n_nodes = in_sizes[0] / F_IN;
    int n_edges = in_sizes[1] / 2;

    k_detect<<<1, 256>>>(edge_index, in_sizes[1], n_nodes);
    k_init_deg<<<(n_nodes + 255) / 256, 256>>>(n_nodes);
    k_degree<<<(n_edges + 255) / 256, 256>>>(edge_index, n_edges);

    k_gemm<<<(n_nodes + GROWS - 1) / GROWS, 256>>>(x, W_conv, n_nodes);

    long long scatter_threads = (long long)n_edges * 8;
    k_scatter<<<(int)((scatter_threads + 255) / 256), 256>>>(edge_index, n_edges);

    k_mlp<<<(n_nodes + 127) / 128, 128>>>(b_conv, W1, b1, W2, b2, W3, b3,
                                          out, n_nodes);
}

// round 11
// speedup vs baseline: 2.2827x; 1.0587x over previous
#include <cuda_runtime.h>
#include <cstdint>

#define N_NODES 100000
#define N_EDGES 1600000
#define F_IN    100
#define F_H     32
#define GROWS   128    // rows per gemm block
#define XPAD    103    // xs row stride (floats): bank-conflict-free broadcast

typedef unsigned long long ull;

// ---------------- scratch (static device globals; no runtime allocs) ---------
__device__ float g_deg [N_NODES];
__device__ float g_dinv[N_NODES];
__device__ __align__(16) float g_hs [(size_t)N_NODES * F_H];  // h * dinv[src]
__device__ __align__(16) float g_agg[(size_t)N_NODES * F_H];  // raw aggregate
__device__ int   g_is32;                                      // 1 if edge_index is int32

__device__ __forceinline__ int edge_at(const void* ei, size_t i, int is32) {
    if (is32) return ((const int*)ei)[i];
    return (int)((const long long*)ei)[i];
}

// packed fp32x2 helpers (sm_100+)
__device__ __forceinline__ void fma2(ull& d, ull a, ull b) {
    asm("fma.rn.f32x2 %0, %1, %2, %0;" : "+l"(d) : "l"(a), "l"(b));
}
__device__ __forceinline__ ull dup2(float v) {
    ull r; asm("mov.b64 %0, {%1, %1};" : "=l"(r) : "f"(v)); return r;
}
__device__ __forceinline__ void unpk(ull v, float& lo, float& hi) {
    asm("mov.b64 {%0, %1}, %2;" : "=f"(lo), "=f"(hi) : "l"(v));
}

// ---------------- K1: deg init + dtype detection (block 0) -------------------
__global__ void k_init_deg(const void* ei, int n_total, int n_nodes) {
    int i = blockIdx.x * blockDim.x + threadIdx.x;
    if (i < n_nodes) g_deg[i] = 1.0f;
    if (blockIdx.x == 0) {
        __shared__ int bad;
        if (threadIdx.x == 0) bad = 0;
        __syncthreads();
        int n_check = n_total < 2048 ? n_total : 2048;
        for (int j = threadIdx.x; j < n_check; j += blockDim.x) {
            long long v = ((const long long*)ei)[j];
            if (v < 0 || v >= (long long)n_nodes) atomicOr(&bad, 1);
        }
        __syncthreads();
        if (threadIdx.x == 0) g_is32 = bad;   // int64-read garbage => int32 data
    }
}

// ---------------- K2: degree accumulation over edges -------------------------
__global__ void k_degree(const void* __restrict__ edge_index, int n_edges) {
    int e = blockIdx.x * blockDim.x + threadIdx.x;
    if (e < n_edges) {
        int dst = edge_at(edge_index, (size_t)n_edges + e, g_is32);
        atomicAdd(&g_deg[dst], 1.0f);
    }
}

// ---------------- K3: GEMM h = x@W, f32x2, smem-staged x ---------------------
// 128 threads; tile 128 rows x 32 cols; thread = 4 rows x 8 cols.
// xs: [128][XPAD] staged coalesced. Ws: [100][32]. Dynamic smem = 64 KB.
__global__ void __launch_bounds__(128) k_gemm(const float* __restrict__ x,
                                              const float* __restrict__ W,
                                              int n_nodes) {
    extern __shared__ __align__(16) float smem[];
    float* xs = smem;                      // GROWS * XPAD floats
    float* Ws = smem + GROWS * XPAD;       // F_IN * F_H floats (16B aligned: 128*103 even mult of 4)
    int tid = threadIdx.x;
    int row0 = blockIdx.x * GROWS;
    int nrow = n_nodes - row0; if (nrow > GROWS) nrow = GROWS;

    // stage W: 800 float4, coalesced
    const float4* W4 = (const float4*)W;
    for (int i = tid; i < (F_IN * F_H) / 4; i += 128)
        ((float4*)Ws)[i] = W4[i];
    // stage x: nrow rows x 25 float4, coalesced reads
    const float4* x4 = (const float4*)x;
    for (int i = tid; i < nrow * (F_IN / 4); i += 128) {
        int r = i / (F_IN / 4), c = i % (F_IN / 4);
        float4 v = x4[(size_t)(row0 + r) * (F_IN / 4) + c];
        float* d = &xs[r * XPAD + c * 4];
        d[0] = v.x; d[1] = v.y; d[2] = v.z; d[3] = v.w;
    }
    __syncthreads();

    int rt = tid >> 2;                 // 0..31
    int cq = tid & 3;                  // col quarter
    int rbase = rt * 4;                // local rows rbase..rbase+3

    ull acc[4][4];
#pragma unroll
    for (int j = 0; j < 4; j++)
#pragma unroll
        for (int p = 0; p < 4; p++) acc[j][p] = 0ull;

    const ulonglong2* Wp = (const ulonglong2*)Ws;
    const float* xr = &xs[rbase * XPAD];

#pragma unroll 4
    for (int k = 0; k < F_IN; k++) {
        ulonglong2 wA = Wp[k * 8 + cq * 2];      // cols cq*8+0..3
        ulonglong2 wB = Wp[k * 8 + cq * 2 + 1];  // cols cq*8+4..7
#pragma unroll
        for (int j = 0; j < 4; j++) {
            ull a = dup2(xr[j * XPAD + k]);
            fma2(acc[j][0], a, wA.x);
            fma2(acc[j][1], a, wA.y);
            fma2(acc[j][2], a, wB.x);
            fma2(acc[j][3], a, wB.y);
        }
    }

    // epilogue: per row, hs = h * dinv; write g_hs and g_agg (self-loop init)
#pragma unroll
    for (int j = 0; j < 4; j++) {
        int row = row0 + rbase + j;
        if (row >= n_nodes) break;
        float dinv = rsqrtf(g_deg[row]);
        if (cq == 0) g_dinv[row] = dinv;
        float o[8];
#pragma unroll
        for (int p = 0; p < 4; p++) unpk(acc[j][p], o[p * 2], o[p * 2 + 1]);
        float4 v0 = {o[0]*dinv, o[1]*dinv, o[2]*dinv, o[3]*dinv};
        float4 v1 = {o[4]*dinv, o[5]*dinv, o[6]*dinv, o[7]*dinv};
        size_t off = (size_t)row * F_H + cq * 8;
        *(float4*)&g_hs [off]     = v0;  *(float4*)&g_hs [off + 4] = v1;
        *(float4*)&g_agg[off]     = v0;  *(float4*)&g_agg[off + 4] = v1;
    }
}

// ---------------- K4: pure gather + vector RED (dinv[dst] deferred) ----------
__global__ void k_scatter(const void* __restrict__ edge_index, int n_edges) {
    int t = blockIdx.x * blockDim.x + threadIdx.x;
    int e = t >> 3;
    int g = t & 7;
    if (e >= n_edges) return;
    int is32 = g_is32;
    int src = edge_at(edge_index, e, is32);
    int dst = edge_at(edge_index, (size_t)n_edges + e, is32);

    const float4* hsv4 = (const float4*)g_hs;
    float4 v = __ldg(&hsv4[(size_t)src * 8 + g]);

    float* p = &g_agg[(size_t)dst * F_H + g * 4];
    asm volatile("red.global.add.v4.f32 [%0], {%1, %2, %3, %4};"
                 :: "l"(p), "f"(v.x), "f"(v.y), "f"(v.z), "f"(v.w)
                 : "memory");
}

// ---------------- K5: dinv scale + bias + relu + MLP + log_softmax -----------
__global__ void k_mlp(const float* __restrict__ b_conv,
                      const float* __restrict__ W1, const float* __restrict__ b1,
                      const float* __restrict__ W2, const float* __restrict__ b2,
                      const float* __restrict__ W3, const float* __restrict__ b3,
                      float* __restrict__ out, int n_nodes) {
    __shared__ float sW1[32 * 16], sb1[16];
    __shared__ float sW2[16 * 8],  sb2[8];
    __shared__ float sW3[8 * 10],  sb3[10];
    __shared__ float sbc[32];
    int tid = threadIdx.x;
    for (int i = tid; i < 32 * 16; i += blockDim.x) sW1[i] = W1[i];
    for (int i = tid; i < 16 * 8;  i += blockDim.x) sW2[i] = W2[i];
    for (int i = tid; i < 8 * 10;  i += blockDim.x) sW3[i] = W3[i];
    if (tid < 16) sb1[tid] = b1[tid];
    if (tid < 8)  sb2[tid] = b2[tid];
    if (tid < 10) sb3[tid] = b3[tid];
    if (tid < 32) sbc[tid] = b_conv[tid];
    __syncthreads();

    int node = blockIdx.x * blockDim.x + tid;
    if (node >= n_nodes) return;

    float dinv = g_dinv[node];
    float a[32];
    const float4* ag4 = (const float4*)(&g_agg[(size_t)node * F_H]);
#pragma unroll
    for (int q = 0; q < 8; q++) {
        float4 v = ag4[q];
        a[q * 4 + 0] = fmaxf(fmaf(v.x, dinv, sbc[q * 4 + 0]), 0.0f);
        a[q * 4 + 1] = fmaxf(fmaf(v.y, dinv, sbc[q * 4 + 1]), 0.0f);
        a[q * 4 + 2] = fmaxf(fmaf(v.z, dinv, sbc[q * 4 + 2]), 0.0f);
        a[q * 4 + 3] = fmaxf(fmaf(v.w, dinv, sbc[q * 4 + 3]), 0.0f);
    }

    float h1[16];
#pragma unroll
    for (int j = 0; j < 16; j++) {
        float s = sb1[j];
#pragma unroll
        for (int k = 0; k < 32; k++) s = fmaf(a[k], sW1[k * 16 + j], s);
        h1[j] = fmaxf(s, 0.0f);
    }
    float h2[8];
#pragma unroll
    for (int j = 0; j < 8; j++) {
        float s = sb2[j];
#pragma unroll
        for (int k = 0; k < 16; k++) s = fmaf(h1[k], sW2[k * 8 + j], s);
        h2[j] = fmaxf(s, 0.0f);
    }
    float z[10];
#pragma unroll
    for (int j = 0; j < 10; j++) {
        float s = sb3[j];
#pragma unroll
        for (int k = 0; k < 8; k++) s = fmaf(h2[k], sW3[k * 10 + j], s);
        z[j] = s;
    }
    float m = z[0];
#pragma unroll
    for (int j = 1; j < 10; j++) m = fmaxf(m, z[j]);
    float sum = 0.0f;
#pragma unroll
    for (int j = 0; j < 10; j++) sum += expf(z[j] - m);
    float lse = logf(sum) + m;
    float* op = out + (size_t)node * 10;
#pragma unroll
    for (int j = 0; j < 10; j++) op[j] = z[j] - lse;
}

// ---------------- launch -----------------------------------------------------
extern "C" void kernel_launch(void* const* d_in, const int* in_sizes, int n_in,
                              void* d_out, int out_size) {
    const float* x          = (const float*)d_in[0];
    const void*  edge_index = (const void*)d_in[1];
    const float* W_conv = (const float*)d_in[3];
    const float* b_conv = (const float*)d_in[4];
    const float* W1 = (const float*)d_in[5];
    const float* b1 = (const float*)d_in[6];
    const float* W2 = (const float*)d_in[7];
    const float* b2 = (const float*)d_in[8];
    const float* W3 = (const float*)d_in[9];
    const float* b3 = (const float*)d_in[10];
    float* out = (float*)d_out;

    int n_nodes = in_sizes[0] / F_IN;
    int n_edges = in_sizes[1] / 2;

    const int gemm_smem = (GROWS * XPAD + F_IN * F_H) * (int)sizeof(float); // 65536 B
    static int attr_done = 0;
    if (!attr_done) {
        cudaFuncSetAttribute(k_gemm, cudaFuncAttributeMaxDynamicSharedMemorySize,
                             gemm_smem);
        attr_done = 1;
    }

    k_init_deg<<<(n_nodes + 255) / 256, 256>>>(edge_index, in_sizes[1], n_nodes);
    k_degree<<<(n_edges + 255) / 256, 256>>>(edge_index, n_edges);

    k_gemm<<<(n_nodes + GROWS - 1) / GROWS, 128, gemm_smem>>>(x, W_conv, n_nodes);

    long long scatter_threads = (long long)n_edges * 8;
    k_scatter<<<(int)((scatter_threads + 255) / 256), 256>>>(edge_index, n_edges);

    k_mlp<<<(n_nodes + 127) / 128, 128>>>(b_conv, W1, b1, W2, b2, W3, b3,
                                          out, n_nodes);
}